// round 15
// baseline (speedup 1.0000x reference)
#include <cuda_runtime.h>
#include <cuda_fp16.h>
#include <cmath>
#include <cstdint>

// Problem constants
constexpr int Bn = 2;
constexpr int Tn = 2048;
constexpr int Cn = 1024;
constexpr int Mn = Bn * Tn;   // 4096
constexpr int WN = Cn * Cn;

// ---------------------------------------------------------------------------
// Scratch (device globals -- no allocation allowed)
// ---------------------------------------------------------------------------
__device__ __align__(256) half g_xh[Mn * Cn];
__device__ __align__(256) half g_wh[4 * WN];     // q,k,v,o weights fp16
__device__ __align__(256) half g_qh[Mn * Cn];
__device__ __align__(256) half g_kh[Mn * Cn];
__device__ __align__(256) half g_vh[Mn * Cn];
__device__ __align__(256) half g_ao[Mn * Cn];

// ---------------------------------------------------------------------------
// PTX helpers (base ISA: cp.async / ldmatrix / mma.sync)
// ---------------------------------------------------------------------------
__device__ __forceinline__ uint32_t smem_u32(const void* p) {
    uint32_t a;
    asm("{ .reg .u64 t; cvta.to.shared.u64 t, %1; cvt.u32.u64 %0, t; }"
        : "=r"(a) : "l"(p));
    return a;
}
__device__ __forceinline__ void cp16(uint32_t s, const void* g) {
    asm volatile("cp.async.cg.shared.global [%0], [%1], 16;" :: "r"(s), "l"(g));
}
__device__ __forceinline__ void ldm_x4(uint32_t& r0, uint32_t& r1,
                                       uint32_t& r2, uint32_t& r3, uint32_t a) {
    asm volatile("ldmatrix.sync.aligned.m8n8.x4.shared.b16 {%0,%1,%2,%3}, [%4];"
                 : "=r"(r0), "=r"(r1), "=r"(r2), "=r"(r3) : "r"(a));
}
__device__ __forceinline__ void ldm_x4_t(uint32_t& r0, uint32_t& r1,
                                         uint32_t& r2, uint32_t& r3, uint32_t a) {
    asm volatile("ldmatrix.sync.aligned.m8n8.x4.trans.shared.b16 {%0,%1,%2,%3}, [%4];"
                 : "=r"(r0), "=r"(r1), "=r"(r2), "=r"(r3) : "r"(a));
}
__device__ __forceinline__ void mma_f16(float* c, const uint32_t* a,
                                        const uint32_t* b) {
    asm volatile(
        "mma.sync.aligned.m16n8k16.row.col.f32.f16.f16.f32 "
        "{%0,%1,%2,%3}, {%4,%5,%6,%7}, {%8,%9}, {%0,%1,%2,%3};"
        : "+f"(c[0]), "+f"(c[1]), "+f"(c[2]), "+f"(c[3])
        : "r"(a[0]), "r"(a[1]), "r"(a[2]), "r"(a[3]), "r"(b[0]), "r"(b[1]));
}
__device__ __forceinline__ uint32_t packh2(float x, float y) {
    half2 h = __floats2half2_rn(x, y);
    return *reinterpret_cast<uint32_t*>(&h);
}

// ---------------------------------------------------------------------------
// Single-pass fp16 GEMM:  out[m][n] = sum_k A[m][k]*W[n][k] + bias[n]
// Tile 128x128, BK=32. 128 threads = 4 warps (2x2), warp tile 64x64.
// 3-stage cp.async ring (48 KB/CTA).
// NCTA=3 (QKV, 768 CTAs): regs<=170, 3 CTAs/SM -- R14 path, unchanged.
// NCTA=2 (O-proj, 256 CTAs, grid-limited): frag software pipeline -- issue
//   ks=1's ldsm before ks=0's mma block so the 2nd ldsm burst hides under
//   32 mmas (intra-warp ILP where warp parallelism is scarce).
// ---------------------------------------------------------------------------
constexpr int GBK = 32;
constexpr int KITERS = Cn / GBK;            // 32
constexpr int TIL = 128 * GBK * 2;          // 8192 bytes per matrix tile
constexpr int STAGES = 3;
constexpr int STG = 2 * TIL;                // A + B per stage = 16 KB
constexpr int SM_GEMM = STAGES * STG;       // 48 KB

template <bool F16OUT, int NCTA>
__global__ void __launch_bounds__(128, NCTA) gemm_f16(
    const half* __restrict__ a, const half* __restrict__ wh,
    const float* __restrict__ b0, const float* __restrict__ b1, const float* __restrict__ b2,
    half* oh0, half* oh1, half* oh2, float* of)
{
    extern __shared__ char smem[];
    const uint32_t sb = smem_u32(smem);
    const int tid = threadIdx.x;
    const int z = blockIdx.z;
    const int m0 = blockIdx.y * 128;
    const int n0 = blockIdx.x * 128;

    const half* Bh = wh + (size_t)z * WN;
    const float* bias = (z == 0) ? b0 : (z == 1) ? b1 : b2;
    half* oh = (z == 0) ? oh0 : (z == 1) ? oh1 : oh2;

    const int lane = tid & 31;
    const int wid = tid >> 5;
    const int wm = wid >> 1;       // 0..1 : 64 rows
    const int wn = wid & 1;        // 0..1 : 64 cols

    const int lr = tid >> 2;       // 0..31
    const int lc = tid & 3;
    uint32_t soff[4];
#pragma unroll
    for (int j = 0; j < 4; j++) {
        int row = lr + 32 * j;
        soff[j] = (uint32_t)(row * 64 + ((lc ^ ((row >> 1) & 3)) << 4));
    }

    auto load_stage = [&](int it, int s) {
        const int k0 = it * GBK;
        const uint32_t st = sb + s * STG;
#pragma unroll
        for (int j = 0; j < 4; j++) {
            int row = lr + 32 * j;
            size_t ga = (size_t)(m0 + row) * Cn + k0 + lc * 8;
            size_t gb = (size_t)(n0 + row) * Cn + k0 + lc * 8;
            cp16(st + soff[j],       a + ga);
            cp16(st + TIL + soff[j], Bh + gb);
        }
        asm volatile("cp.async.commit_group;" ::: "memory");
    };

    const int arow = wm * 64 + (lane & 15);
    const int brow = wn * 64 + (lane & 7) + ((lane >> 4) << 3);

    float acc[4][8][4];
#pragma unroll
    for (int i = 0; i < 4; i++)
#pragma unroll
        for (int j = 0; j < 8; j++)
#pragma unroll
            for (int r = 0; r < 4; r++) acc[i][j][r] = 0.0f;

    load_stage(0, 0);
    load_stage(1, 1);

    int st_it = 0;
    int st_ld = 2;

    for (int it = 0; it < KITERS; it++) {
        asm volatile("cp.async.wait_group 1;" ::: "memory");
        __syncthreads();
        if (it + 2 < KITERS)
            load_stage(it + 2, st_ld);

        const uint32_t st = sb + st_it * STG;
        st_it = (st_it == 2) ? 0 : st_it + 1;
        st_ld = (st_ld == 2) ? 0 : st_ld + 1;

        if constexpr (NCTA == 2) {
            // ---- frag software pipeline (reg budget 255 allows 2x frags) ----
            uint32_t fah[2][4][4], fbh[2][8][2];
            auto load_frags = [&](int ks) {
                const int akc = ks * 2 + (lane >> 4);
#pragma unroll
                for (int mi = 0; mi < 4; mi++) {
                    int row = arow + mi * 16;
                    uint32_t off = (uint32_t)(row * 64 + ((akc ^ ((row >> 1) & 3)) << 4));
                    ldm_x4(fah[ks][mi][0], fah[ks][mi][1], fah[ks][mi][2], fah[ks][mi][3],
                           st + off);
                }
                const int bkc = ks * 2 + ((lane >> 3) & 1);
#pragma unroll
                for (int p = 0; p < 4; p++) {
                    int row = brow + p * 16;
                    uint32_t off = (uint32_t)(row * 64 + ((bkc ^ ((row >> 1) & 3)) << 4));
                    ldm_x4(fbh[ks][2 * p][0], fbh[ks][2 * p][1],
                           fbh[ks][2 * p + 1][0], fbh[ks][2 * p + 1][1],
                           st + TIL + off);
                }
            };
            load_frags(0);
            load_frags(1);   // issued before any mma: burst hides under mma(ks=0)
#pragma unroll
            for (int ks = 0; ks < 2; ks++)
#pragma unroll
                for (int mi = 0; mi < 4; mi++)
#pragma unroll
                    for (int ni = 0; ni < 8; ni++)
                        mma_f16(acc[mi][ni], fah[ks][mi], fbh[ks][ni]);
        } else {
            // ---- R14 path (reg-capped NCTA=3): serial ks phases ----
#pragma unroll
            for (int ks = 0; ks < 2; ks++) {
                uint32_t fah[4][4], fbh[8][2];
                const int akc = ks * 2 + (lane >> 4);
#pragma unroll
                for (int mi = 0; mi < 4; mi++) {
                    int row = arow + mi * 16;
                    uint32_t off = (uint32_t)(row * 64 + ((akc ^ ((row >> 1) & 3)) << 4));
                    ldm_x4(fah[mi][0], fah[mi][1], fah[mi][2], fah[mi][3], st + off);
                }
                const int bkc = ks * 2 + ((lane >> 3) & 1);
#pragma unroll
                for (int p = 0; p < 4; p++) {
                    int row = brow + p * 16;
                    uint32_t off = (uint32_t)(row * 64 + ((bkc ^ ((row >> 1) & 3)) << 4));
                    ldm_x4(fbh[2 * p][0], fbh[2 * p][1], fbh[2 * p + 1][0], fbh[2 * p + 1][1],
                           st + TIL + off);
                }
#pragma unroll
                for (int mi = 0; mi < 4; mi++)
#pragma unroll
                    for (int ni = 0; ni < 8; ni++)
                        mma_f16(acc[mi][ni], fah[mi], fbh[ni]);
            }
        }
    }

#pragma unroll
    for (int mi = 0; mi < 4; mi++) {
#pragma unroll
        for (int hh = 0; hh < 2; hh++) {
            int row = m0 + wm * 64 + mi * 16 + (lane >> 2) + hh * 8;
#pragma unroll
            for (int ni = 0; ni < 8; ni++) {
                int col = n0 + wn * 64 + ni * 8 + (lane & 3) * 2;
                float vx = acc[mi][ni][hh * 2 + 0] + bias[col];
                float vy = acc[mi][ni][hh * 2 + 1] + bias[col + 1];
                if (F16OUT) {
                    *(half2*)&oh[(size_t)row * Cn + col] = __floats2half2_rn(vx, vy);
                } else {
                    float2 o; o.x = vx; o.y = vy;
                    *(float2*)&of[(size_t)row * Cn + col] = o;
                }
            }
        }
    }
}

// ---------------------------------------------------------------------------
// Merged converter, 8 floats/thread: z 0..3 -> weights, z 4..7 -> x quarters.
// ---------------------------------------------------------------------------
__global__ void __launch_bounds__(256) convert_all(
    const float* __restrict__ x,
    const float* __restrict__ w0, const float* __restrict__ w1,
    const float* __restrict__ w2, const float* __restrict__ w3,
    half* __restrict__ xh, half* __restrict__ wh)
{
    const int z = blockIdx.y;
    int i = (blockIdx.x * 256 + threadIdx.x) * 8;
    const float* src;
    half* dst;
    if (z >= 4) {
        src = x + (size_t)(z - 4) * WN;  dst = xh + (size_t)(z - 4) * WN;
    } else {
        src = (z == 0) ? w0 : (z == 1) ? w1 : (z == 2) ? w2 : w3;
        dst = wh + (size_t)z * WN;
    }
#pragma unroll
    for (int u = 0; u < 2; u++) {
        float4 v = *(const float4*)&src[i + u * 4];
        *(half2*)&dst[i + u * 4]     = __floats2half2_rn(v.x, v.y);
        *(half2*)&dst[i + u * 4 + 2] = __floats2half2_rn(v.z, v.w);
    }
}

// ---------------------------------------------------------------------------
// MMA band attention, warp-autonomous (R14 winner, unchanged).
// Block = 64 queries of one (b,h); keys [q0-32, q0+96); 128 threads = 4 warps.
// Warp w owns queries [q0+16w, q0+16w+16) over ALL 128 band keys.
// ---------------------------------------------------------------------------
constexpr int ASM_QH = 0;          // 8 KB
constexpr int ASM_KH = 8192;       // 16 KB
constexpr int ASM_VH = 24576;      // 16 KB
constexpr int ASM_TOTAL = 40960;

__device__ __forceinline__ uint32_t swz(int row, int chunk) {
    return (uint32_t)(row * 128 + ((chunk ^ (row & 7)) << 4));
}

__global__ void __launch_bounds__(128, 3) attn_mma(
    const half* __restrict__ qh, const half* __restrict__ kh,
    const half* __restrict__ vh, half* __restrict__ ao)
{
    extern __shared__ char smem[];
    const uint32_t sb = smem_u32(smem);

    const int tid = threadIdx.x;
    const int lane = tid & 31;
    const int w = tid >> 5;         // 0..3 : queries [16w, 16w+16)
    const int bh = blockIdx.y;
    const int b = bh >> 4;
    const int h = bh & 15;
    const int q0 = blockIdx.x * 64;

    for (int id = tid; id < 64 * 8; id += 128) {
        int r = id >> 3, c = id & 7;
        size_t g = ((size_t)(b * Tn + q0 + r)) * Cn + h * 64 + c * 8;
        cp16(sb + ASM_QH + swz(r, c), qh + g);
    }
    for (int id = tid; id < 128 * 8; id += 128) {
        int r = id >> 3, c = id & 7;
        int tok = q0 - 32 + r;
        tok = tok < 0 ? 0 : (tok >= Tn ? Tn - 1 : tok);
        uint32_t so = swz(r, c);
        size_t g = ((size_t)(b * Tn + tok)) * Cn + h * 64 + c * 8;
        cp16(sb + ASM_KH + so, kh + g);
        cp16(sb + ASM_VH + so, vh + g);
    }
    asm volatile("cp.async.commit_group;" ::: "memory");
    asm volatile("cp.async.wait_group 0;" ::: "memory");
    __syncthreads();

    const int bandlo = w * 16;
    const int bandhi = w * 16 + 80;
    auto live = [&](int nt) {
        int c0 = nt * 8;
        return (c0 + 8 > bandlo) && (c0 < bandhi);
    };

    float sacc[16][4];
#pragma unroll
    for (int i = 0; i < 16; i++)
#pragma unroll
        for (int j = 0; j < 4; j++) sacc[i][j] = 0.0f;

    const int aQrow = w * 16 + (lane & 15);
    const int aQc = lane >> 4;
    const int bKrow = (lane & 7) + ((lane >> 4) << 3);
    const int bKc = (lane >> 3) & 1;

#pragma unroll
    for (int kc = 0; kc < 4; kc++) {
        uint32_t fah[4];
        ldm_x4(fah[0], fah[1], fah[2], fah[3],
               sb + ASM_QH + swz(aQrow, kc * 2 + aQc));
        uint32_t fbh[16][2];
#pragma unroll
        for (int p = 0; p < 8; p++) {
            if (live(2 * p) || live(2 * p + 1)) {
                uint32_t off = swz(bKrow + p * 16, kc * 2 + bKc);
                ldm_x4(fbh[2 * p][0], fbh[2 * p][1], fbh[2 * p + 1][0], fbh[2 * p + 1][1],
                       sb + ASM_KH + off);
            }
        }
#pragma unroll
        for (int nt = 0; nt < 16; nt++)
            if (live(nt)) mma_f16(sacc[nt], fah, fbh[nt]);
    }

    const int r0 = lane >> 2;
    const int qg0 = q0 + w * 16 + r0;
    const int qg1 = qg0 + 8;
    float mx[2] = {-1e30f, -1e30f};
#pragma unroll
    for (int nt = 0; nt < 16; nt++) {
        if (live(nt)) {
            int cb = nt * 8 + (lane & 3) * 2;
#pragma unroll
            for (int i = 0; i < 4; i++) {
                int qq = (i < 2) ? qg0 : qg1;
                int jj = q0 - 32 + cb + (i & 1);
                bool ok = (jj >= qq - 32) && (jj < qq + 32) && (jj >= 0) && (jj < Tn);
                float s = ok ? sacc[nt][i] * 0.125f : -1e30f;
                sacc[nt][i] = s;
                mx[i >> 1] = fmaxf(mx[i >> 1], s);
            }
        } else {
#pragma unroll
            for (int i = 0; i < 4; i++) sacc[nt][i] = -1e30f;
        }
    }
#pragma unroll
    for (int j = 0; j < 2; j++) {
        mx[j] = fmaxf(mx[j], __shfl_xor_sync(0xffffffffu, mx[j], 1));
        mx[j] = fmaxf(mx[j], __shfl_xor_sync(0xffffffffu, mx[j], 2));
    }

    float sm[2] = {0.0f, 0.0f};
#pragma unroll
    for (int nt = 0; nt < 16; nt++) {
        if (live(nt)) {
#pragma unroll
            for (int i = 0; i < 4; i++) {
                float p = __expf(sacc[nt][i] - mx[i >> 1]);
                sacc[nt][i] = p;
                sm[i >> 1] += p;
            }
        } else {
#pragma unroll
            for (int i = 0; i < 4; i++) sacc[nt][i] = 0.0f;
        }
    }
#pragma unroll
    for (int j = 0; j < 2; j++) {
        sm[j] += __shfl_xor_sync(0xffffffffu, sm[j], 1);
        sm[j] += __shfl_xor_sync(0xffffffffu, sm[j], 2);
    }
    const float inv0 = 1.0f / sm[0];
    const float inv1 = 1.0f / sm[1];

    float oacc[8][4];
#pragma unroll
    for (int i = 0; i < 8; i++)
#pragma unroll
        for (int j = 0; j < 4; j++) oacc[i][j] = 0.0f;

    const int vrow = ((lane >> 3) & 1) * 8 + (lane & 7);
    const int vc = lane >> 4;

#pragma unroll
    for (int kc = 0; kc < 8; kc++) {
        const int nt0 = 2 * kc, nt1 = 2 * kc + 1;
        if (!(live(nt0) || live(nt1))) continue;
        uint32_t pah[4], pal[4];
        float ps[8] = {sacc[nt0][0], sacc[nt0][1], sacc[nt0][2], sacc[nt0][3],
                       sacc[nt1][0], sacc[nt1][1], sacc[nt1][2], sacc[nt1][3]};
        float pl[8];
#pragma unroll
        for (int i = 0; i < 8; i++) {
            half hv = __float2half_rn(ps[i]);
            pl[i] = ps[i] - __half2float(hv);
        }
        pah[0] = packh2(ps[0], ps[1]); pah[1] = packh2(ps[2], ps[3]);
        pah[2] = packh2(ps[4], ps[5]); pah[3] = packh2(ps[6], ps[7]);
        pal[0] = packh2(pl[0], pl[1]); pal[1] = packh2(pl[2], pl[3]);
        pal[2] = packh2(pl[4], pl[5]); pal[3] = packh2(pl[6], pl[7]);
        uint32_t fvh[8][2];
#pragma unroll
        for (int p = 0; p < 4; p++) {
            uint32_t off = swz(vrow + kc * 16, p * 2 + vc);
            ldm_x4_t(fvh[2 * p][0], fvh[2 * p][1], fvh[2 * p + 1][0], fvh[2 * p + 1][1],
                     sb + ASM_VH + off);
        }
#pragma unroll
        for (int nd = 0; nd < 8; nd++) {
            mma_f16(oacc[nd], pah, fvh[nd]);
            mma_f16(oacc[nd], pal, fvh[nd]);
        }
    }

#pragma unroll
    for (int nd = 0; nd < 8; nd++) {
        int d0 = nd * 8 + (lane & 3) * 2;
        size_t g0 = ((size_t)(b * Tn + qg0)) * Cn + h * 64 + d0;
        size_t g1 = ((size_t)(b * Tn + qg1)) * Cn + h * 64 + d0;
        *(half2*)&ao[g0] = __floats2half2_rn(oacc[nd][0] * inv0, oacc[nd][1] * inv0);
        *(half2*)&ao[g1] = __floats2half2_rn(oacc[nd][2] * inv1, oacc[nd][3] * inv1);
    }
}

// ---------------------------------------------------------------------------
extern "C" void kernel_launch(void* const* d_in, const int* in_sizes, int n_in,
                              void* d_out, int out_size)
{
    const float* x   = (const float*)d_in[0];
    const float* q_w = (const float*)d_in[1];
    const float* q_b = (const float*)d_in[2];
    const float* k_w = (const float*)d_in[3];
    const float* k_b = (const float*)d_in[4];
    const float* v_w = (const float*)d_in[5];
    const float* v_b = (const float*)d_in[6];
    const float* o_w = (const float*)d_in[7];
    const float* o_b = (const float*)d_in[8];
    float* out = (float*)d_out;

    half *xh, *wh, *pqh, *pkh, *pvh, *pao;
    cudaGetSymbolAddress((void**)&xh, g_xh);
    cudaGetSymbolAddress((void**)&wh, g_wh);
    cudaGetSymbolAddress((void**)&pqh, g_qh);
    cudaGetSymbolAddress((void**)&pkh, g_kh);
    cudaGetSymbolAddress((void**)&pvh, g_vh);
    cudaGetSymbolAddress((void**)&pao, g_ao);

    cudaFuncSetAttribute((const void*)gemm_f16<true, 3>,
                         cudaFuncAttributeMaxDynamicSharedMemorySize, SM_GEMM);
    cudaFuncSetAttribute((const void*)gemm_f16<false, 2>,
                         cudaFuncAttributeMaxDynamicSharedMemorySize, SM_GEMM);
    cudaFuncSetAttribute((const void*)attn_mma,
                         cudaFuncAttributeMaxDynamicSharedMemorySize, ASM_TOTAL);

    dim3 cgrid(WN / 2048, 8);   // z 0..3 weights, 4..7 x quarters
    convert_all<<<cgrid, 256>>>(x, q_w, k_w, v_w, o_w, xh, wh);

    dim3 qkv_grid(Cn / 128, Mn / 128, 3);
    gemm_f16<true, 3><<<qkv_grid, 128, SM_GEMM>>>(
        xh, wh, q_b, k_b, v_b, pqh, pkh, pvh, nullptr);

    dim3 attn_grid(Tn / 64, Bn * 16);
    attn_mma<<<attn_grid, 128, ASM_TOTAL>>>(pqh, pkh, pvh, pao);

    dim3 o_grid(Cn / 128, Mn / 128, 1);
    gemm_f16<false, 2><<<o_grid, 128, SM_GEMM>>>(
        pao, wh + 3 * (size_t)WN, o_b, o_b, o_b,
        nullptr, nullptr, nullptr, out);
}

// round 16
// speedup vs baseline: 1.0338x; 1.0338x over previous
#include <cuda_runtime.h>
#include <cuda_fp16.h>
#include <cmath>
#include <cstdint>

// Problem constants
constexpr int Bn = 2;
constexpr int Tn = 2048;
constexpr int Cn = 1024;
constexpr int Mn = Bn * Tn;   // 4096
constexpr int WN = Cn * Cn;

// ---------------------------------------------------------------------------
// Scratch (device globals -- no allocation allowed)
// ---------------------------------------------------------------------------
__device__ __align__(256) half g_xh[Mn * Cn];
__device__ __align__(256) half g_wh[4 * WN];     // q,k,v,o weights fp16
__device__ __align__(256) half g_qh[Mn * Cn];
__device__ __align__(256) half g_kh[Mn * Cn];
__device__ __align__(256) half g_vh[Mn * Cn];
__device__ __align__(256) half g_ao[Mn * Cn];

// ---------------------------------------------------------------------------
// PTX helpers (base ISA: cp.async / ldmatrix / mma.sync)
// ---------------------------------------------------------------------------
__device__ __forceinline__ uint32_t smem_u32(const void* p) {
    uint32_t a;
    asm("{ .reg .u64 t; cvta.to.shared.u64 t, %1; cvt.u32.u64 %0, t; }"
        : "=r"(a) : "l"(p));
    return a;
}
__device__ __forceinline__ void cp16(uint32_t s, const void* g) {
    asm volatile("cp.async.cg.shared.global [%0], [%1], 16;" :: "r"(s), "l"(g));
}
__device__ __forceinline__ void ldm_x4(uint32_t& r0, uint32_t& r1,
                                       uint32_t& r2, uint32_t& r3, uint32_t a) {
    asm volatile("ldmatrix.sync.aligned.m8n8.x4.shared.b16 {%0,%1,%2,%3}, [%4];"
                 : "=r"(r0), "=r"(r1), "=r"(r2), "=r"(r3) : "r"(a));
}
__device__ __forceinline__ void ldm_x4_t(uint32_t& r0, uint32_t& r1,
                                         uint32_t& r2, uint32_t& r3, uint32_t a) {
    asm volatile("ldmatrix.sync.aligned.m8n8.x4.trans.shared.b16 {%0,%1,%2,%3}, [%4];"
                 : "=r"(r0), "=r"(r1), "=r"(r2), "=r"(r3) : "r"(a));
}
__device__ __forceinline__ void mma_f16(float* c, const uint32_t* a,
                                        const uint32_t* b) {
    asm volatile(
        "mma.sync.aligned.m16n8k16.row.col.f32.f16.f16.f32 "
        "{%0,%1,%2,%3}, {%4,%5,%6,%7}, {%8,%9}, {%0,%1,%2,%3};"
        : "+f"(c[0]), "+f"(c[1]), "+f"(c[2]), "+f"(c[3])
        : "r"(a[0]), "r"(a[1]), "r"(a[2]), "r"(a[3]), "r"(b[0]), "r"(b[1]));
}
__device__ __forceinline__ uint32_t packh2(float x, float y) {
    half2 h = __floats2half2_rn(x, y);
    return *reinterpret_cast<uint32_t*>(&h);
}

// ---------------------------------------------------------------------------
// Single-pass fp16 GEMM (R15 winner, unchanged):
// Tile 128x128, BK=32, 128 threads (4 warps 2x2), warp tile 64x64,
// 3-stage cp.async ring. NCTA=3: QKV (3 CTAs/SM). NCTA=2: O-proj with
// frag software pipeline.
// ---------------------------------------------------------------------------
constexpr int GBK = 32;
constexpr int KITERS = Cn / GBK;            // 32
constexpr int TIL = 128 * GBK * 2;          // 8192 bytes per matrix tile
constexpr int STAGES = 3;
constexpr int STG = 2 * TIL;                // A + B per stage = 16 KB
constexpr int SM_GEMM = STAGES * STG;       // 48 KB

template <bool F16OUT, int NCTA>
__global__ void __launch_bounds__(128, NCTA) gemm_f16(
    const half* __restrict__ a, const half* __restrict__ wh,
    const float* __restrict__ b0, const float* __restrict__ b1, const float* __restrict__ b2,
    half* oh0, half* oh1, half* oh2, float* of)
{
    extern __shared__ char smem[];
    const uint32_t sb = smem_u32(smem);
    const int tid = threadIdx.x;
    const int z = blockIdx.z;
    const int m0 = blockIdx.y * 128;
    const int n0 = blockIdx.x * 128;

    const half* Bh = wh + (size_t)z * WN;
    const float* bias = (z == 0) ? b0 : (z == 1) ? b1 : b2;
    half* oh = (z == 0) ? oh0 : (z == 1) ? oh1 : oh2;

    const int lane = tid & 31;
    const int wid = tid >> 5;
    const int wm = wid >> 1;
    const int wn = wid & 1;

    const int lr = tid >> 2;
    const int lc = tid & 3;
    uint32_t soff[4];
#pragma unroll
    for (int j = 0; j < 4; j++) {
        int row = lr + 32 * j;
        soff[j] = (uint32_t)(row * 64 + ((lc ^ ((row >> 1) & 3)) << 4));
    }

    auto load_stage = [&](int it, int s) {
        const int k0 = it * GBK;
        const uint32_t st = sb + s * STG;
#pragma unroll
        for (int j = 0; j < 4; j++) {
            int row = lr + 32 * j;
            size_t ga = (size_t)(m0 + row) * Cn + k0 + lc * 8;
            size_t gb = (size_t)(n0 + row) * Cn + k0 + lc * 8;
            cp16(st + soff[j],       a + ga);
            cp16(st + TIL + soff[j], Bh + gb);
        }
        asm volatile("cp.async.commit_group;" ::: "memory");
    };

    const int arow = wm * 64 + (lane & 15);
    const int brow = wn * 64 + (lane & 7) + ((lane >> 4) << 3);

    float acc[4][8][4];
#pragma unroll
    for (int i = 0; i < 4; i++)
#pragma unroll
        for (int j = 0; j < 8; j++)
#pragma unroll
            for (int r = 0; r < 4; r++) acc[i][j][r] = 0.0f;

    load_stage(0, 0);
    load_stage(1, 1);

    int st_it = 0;
    int st_ld = 2;

    for (int it = 0; it < KITERS; it++) {
        asm volatile("cp.async.wait_group 1;" ::: "memory");
        __syncthreads();
        if (it + 2 < KITERS)
            load_stage(it + 2, st_ld);

        const uint32_t st = sb + st_it * STG;
        st_it = (st_it == 2) ? 0 : st_it + 1;
        st_ld = (st_ld == 2) ? 0 : st_ld + 1;

        if constexpr (NCTA == 2) {
            uint32_t fah[2][4][4], fbh[2][8][2];
            auto load_frags = [&](int ks) {
                const int akc = ks * 2 + (lane >> 4);
#pragma unroll
                for (int mi = 0; mi < 4; mi++) {
                    int row = arow + mi * 16;
                    uint32_t off = (uint32_t)(row * 64 + ((akc ^ ((row >> 1) & 3)) << 4));
                    ldm_x4(fah[ks][mi][0], fah[ks][mi][1], fah[ks][mi][2], fah[ks][mi][3],
                           st + off);
                }
                const int bkc = ks * 2 + ((lane >> 3) & 1);
#pragma unroll
                for (int p = 0; p < 4; p++) {
                    int row = brow + p * 16;
                    uint32_t off = (uint32_t)(row * 64 + ((bkc ^ ((row >> 1) & 3)) << 4));
                    ldm_x4(fbh[ks][2 * p][0], fbh[ks][2 * p][1],
                           fbh[ks][2 * p + 1][0], fbh[ks][2 * p + 1][1],
                           st + TIL + off);
                }
            };
            load_frags(0);
            load_frags(1);
#pragma unroll
            for (int ks = 0; ks < 2; ks++)
#pragma unroll
                for (int mi = 0; mi < 4; mi++)
#pragma unroll
                    for (int ni = 0; ni < 8; ni++)
                        mma_f16(acc[mi][ni], fah[ks][mi], fbh[ks][ni]);
        } else {
#pragma unroll
            for (int ks = 0; ks < 2; ks++) {
                uint32_t fah[4][4], fbh[8][2];
                const int akc = ks * 2 + (lane >> 4);
#pragma unroll
                for (int mi = 0; mi < 4; mi++) {
                    int row = arow + mi * 16;
                    uint32_t off = (uint32_t)(row * 64 + ((akc ^ ((row >> 1) & 3)) << 4));
                    ldm_x4(fah[mi][0], fah[mi][1], fah[mi][2], fah[mi][3], st + off);
                }
                const int bkc = ks * 2 + ((lane >> 3) & 1);
#pragma unroll
                for (int p = 0; p < 4; p++) {
                    int row = brow + p * 16;
                    uint32_t off = (uint32_t)(row * 64 + ((bkc ^ ((row >> 1) & 3)) << 4));
                    ldm_x4(fbh[2 * p][0], fbh[2 * p][1], fbh[2 * p + 1][0], fbh[2 * p + 1][1],
                           st + TIL + off);
                }
#pragma unroll
                for (int mi = 0; mi < 4; mi++)
#pragma unroll
                    for (int ni = 0; ni < 8; ni++)
                        mma_f16(acc[mi][ni], fah[mi], fbh[ni]);
            }
        }
    }

#pragma unroll
    for (int mi = 0; mi < 4; mi++) {
#pragma unroll
        for (int hh = 0; hh < 2; hh++) {
            int row = m0 + wm * 64 + mi * 16 + (lane >> 2) + hh * 8;
#pragma unroll
            for (int ni = 0; ni < 8; ni++) {
                int col = n0 + wn * 64 + ni * 8 + (lane & 3) * 2;
                float vx = acc[mi][ni][hh * 2 + 0] + bias[col];
                float vy = acc[mi][ni][hh * 2 + 1] + bias[col + 1];
                if (F16OUT) {
                    *(half2*)&oh[(size_t)row * Cn + col] = __floats2half2_rn(vx, vy);
                } else {
                    float2 o; o.x = vx; o.y = vy;
                    *(float2*)&of[(size_t)row * Cn + col] = o;
                }
            }
        }
    }
}

// ---------------------------------------------------------------------------
// Merged converter, 8 floats/thread: z 0..3 -> weights, z 4..7 -> x quarters.
// ---------------------------------------------------------------------------
__global__ void __launch_bounds__(256) convert_all(
    const float* __restrict__ x,
    const float* __restrict__ w0, const float* __restrict__ w1,
    const float* __restrict__ w2, const float* __restrict__ w3,
    half* __restrict__ xh, half* __restrict__ wh)
{
    const int z = blockIdx.y;
    int i = (blockIdx.x * 256 + threadIdx.x) * 8;
    const float* src;
    half* dst;
    if (z >= 4) {
        src = x + (size_t)(z - 4) * WN;  dst = xh + (size_t)(z - 4) * WN;
    } else {
        src = (z == 0) ? w0 : (z == 1) ? w1 : (z == 2) ? w2 : w3;
        dst = wh + (size_t)z * WN;
    }
#pragma unroll
    for (int u = 0; u < 2; u++) {
        float4 v = *(const float4*)&src[i + u * 4];
        *(half2*)&dst[i + u * 4]     = __floats2half2_rn(v.x, v.y);
        *(half2*)&dst[i + u * 4 + 2] = __floats2half2_rn(v.z, v.w);
    }
}

// ---------------------------------------------------------------------------
// MMA band attention, warp-autonomous, 128-query block.
// Block = 128 queries of one (b,h); 256 threads = 8 warps. Staged K/V rows
// [q0-32, q0+160) = 192 rows (25% less global K/V traffic than 64-q blocks).
// Warp w owns queries [q0+16w, +16): its 80-key band = staged rows
// [16w, 16w+80) = exactly 10 S-tiles / 5 PV-pairs -- no dead-tile branches.
// Softmax in quad shuffles only; O accumulates and stores warp-privately.
// mma sequence per query identical to R14 -> bit-identical numerics.
// ---------------------------------------------------------------------------
constexpr int ASM_QH = 0;          // 16 KB (128 rows)
constexpr int ASM_KH = 16384;      // 24 KB (192 rows)
constexpr int ASM_VH = 40960;      // 24 KB (192 rows)
constexpr int ASM_TOTAL = 65536;

__device__ __forceinline__ uint32_t swz(int row, int chunk) {
    return (uint32_t)(row * 128 + ((chunk ^ (row & 7)) << 4));
}

__global__ void __launch_bounds__(256, 2) attn_mma(
    const half* __restrict__ qh, const half* __restrict__ kh,
    const half* __restrict__ vh, half* __restrict__ ao)
{
    extern __shared__ char smem[];
    const uint32_t sb = smem_u32(smem);

    const int tid = threadIdx.x;
    const int lane = tid & 31;
    const int w = tid >> 5;         // 0..7 : queries [16w, 16w+16)
    const int bh = blockIdx.y;
    const int b = bh >> 4;
    const int h = bh & 15;
    const int q0 = blockIdx.x * 128;

    // ---- stage Q (128 rows) and K/V (192 rows), swizzled 128B rows ----
    for (int id = tid; id < 128 * 8; id += 256) {
        int r = id >> 3, c = id & 7;
        size_t g = ((size_t)(b * Tn + q0 + r)) * Cn + h * 64 + c * 8;
        cp16(sb + ASM_QH + swz(r, c), qh + g);
    }
    for (int id = tid; id < 192 * 8; id += 256) {
        int r = id >> 3, c = id & 7;
        int tok = q0 - 32 + r;
        tok = tok < 0 ? 0 : (tok >= Tn ? Tn - 1 : tok);
        uint32_t so = swz(r, c);
        size_t g = ((size_t)(b * Tn + tok)) * Cn + h * 64 + c * 8;
        cp16(sb + ASM_KH + so, kh + g);
        cp16(sb + ASM_VH + so, vh + g);
    }
    asm volatile("cp.async.commit_group;" ::: "memory");
    asm volatile("cp.async.wait_group 0;" ::: "memory");
    __syncthreads();

    // ---- S = Q K^T over this warp's 10 key-tiles (staged rows 16w..16w+80) ----
    float sacc[10][4];
#pragma unroll
    for (int i = 0; i < 10; i++)
#pragma unroll
        for (int j = 0; j < 4; j++) sacc[i][j] = 0.0f;

    const int aQrow = w * 16 + (lane & 15);
    const int aQc = lane >> 4;
    const int bKrow = w * 16 + (lane & 7) + ((lane >> 4) << 3);
    const int bKc = (lane >> 3) & 1;

#pragma unroll
    for (int kc = 0; kc < 4; kc++) {
        uint32_t fah[4];
        ldm_x4(fah[0], fah[1], fah[2], fah[3],
               sb + ASM_QH + swz(aQrow, kc * 2 + aQc));
        uint32_t fbh[10][2];
#pragma unroll
        for (int p = 0; p < 5; p++) {
            uint32_t off = swz(bKrow + p * 16, kc * 2 + bKc);
            ldm_x4(fbh[2 * p][0], fbh[2 * p][1], fbh[2 * p + 1][0], fbh[2 * p + 1][1],
                   sb + ASM_KH + off);
        }
#pragma unroll
        for (int nt = 0; nt < 10; nt++)
            mma_f16(sacc[nt], fah, fbh[nt]);
    }

    // ---- mask + scale + row max (quad shuffles only) ----
    const int r0 = lane >> 2;
    const int qg0 = q0 + w * 16 + r0;
    const int qg1 = qg0 + 8;
    float mx[2] = {-1e30f, -1e30f};
#pragma unroll
    for (int nt = 0; nt < 10; nt++) {
        int cb = w * 16 + nt * 8 + (lane & 3) * 2;   // staged row of this elem
#pragma unroll
        for (int i = 0; i < 4; i++) {
            int qq = (i < 2) ? qg0 : qg1;
            int jj = q0 - 32 + cb + (i & 1);
            bool ok = (jj >= qq - 32) && (jj < qq + 32) && (jj >= 0) && (jj < Tn);
            float s = ok ? sacc[nt][i] * 0.125f : -1e30f;
            sacc[nt][i] = s;
            mx[i >> 1] = fmaxf(mx[i >> 1], s);
        }
    }
#pragma unroll
    for (int j = 0; j < 2; j++) {
        mx[j] = fmaxf(mx[j], __shfl_xor_sync(0xffffffffu, mx[j], 1));
        mx[j] = fmaxf(mx[j], __shfl_xor_sync(0xffffffffu, mx[j], 2));
    }

    // ---- exp + row sum ----
    float sm[2] = {0.0f, 0.0f};
#pragma unroll
    for (int nt = 0; nt < 10; nt++) {
#pragma unroll
        for (int i = 0; i < 4; i++) {
            float p = __expf(sacc[nt][i] - mx[i >> 1]);
            sacc[nt][i] = p;
            sm[i >> 1] += p;
        }
    }
#pragma unroll
    for (int j = 0; j < 2; j++) {
        sm[j] += __shfl_xor_sync(0xffffffffu, sm[j], 1);
        sm[j] += __shfl_xor_sync(0xffffffffu, sm[j], 2);
    }
    const float inv0 = 1.0f / sm[0];
    const float inv1 = 1.0f / sm[1];

    // ---- O = P V over the warp's 80 keys (5 pairs), P hi/lo 2-pass ----
    float oacc[8][4];
#pragma unroll
    for (int i = 0; i < 8; i++)
#pragma unroll
        for (int j = 0; j < 4; j++) oacc[i][j] = 0.0f;

    const int vrow = w * 16 + ((lane >> 3) & 1) * 8 + (lane & 7);
    const int vc = lane >> 4;

#pragma unroll
    for (int kc = 0; kc < 5; kc++) {
        const int nt0 = 2 * kc, nt1 = 2 * kc + 1;
        uint32_t pah[4], pal[4];
        float ps[8] = {sacc[nt0][0], sacc[nt0][1], sacc[nt0][2], sacc[nt0][3],
                       sacc[nt1][0], sacc[nt1][1], sacc[nt1][2], sacc[nt1][3]};
        float pl[8];
#pragma unroll
        for (int i = 0; i < 8; i++) {
            half hv = __float2half_rn(ps[i]);
            pl[i] = ps[i] - __half2float(hv);
        }
        pah[0] = packh2(ps[0], ps[1]); pah[1] = packh2(ps[2], ps[3]);
        pah[2] = packh2(ps[4], ps[5]); pah[3] = packh2(ps[6], ps[7]);
        pal[0] = packh2(pl[0], pl[1]); pal[1] = packh2(pl[2], pl[3]);
        pal[2] = packh2(pl[4], pl[5]); pal[3] = packh2(pl[6], pl[7]);
        uint32_t fvh[8][2];
#pragma unroll
        for (int p = 0; p < 4; p++) {
            uint32_t off = swz(vrow + kc * 16, p * 2 + vc);
            ldm_x4_t(fvh[2 * p][0], fvh[2 * p][1], fvh[2 * p + 1][0], fvh[2 * p + 1][1],
                     sb + ASM_VH + off);
        }
#pragma unroll
        for (int nd = 0; nd < 8; nd++) {
            mma_f16(oacc[nd], pah, fvh[nd]);
            mma_f16(oacc[nd], pal, fvh[nd]);
        }
    }

    // ---- normalize + store (warp-private rows; no cross-warp combine) ----
#pragma unroll
    for (int nd = 0; nd < 8; nd++) {
        int d0 = nd * 8 + (lane & 3) * 2;
        size_t g0 = ((size_t)(b * Tn + qg0)) * Cn + h * 64 + d0;
        size_t g1 = ((size_t)(b * Tn + qg1)) * Cn + h * 64 + d0;
        *(half2*)&ao[g0] = __floats2half2_rn(oacc[nd][0] * inv0, oacc[nd][1] * inv0);
        *(half2*)&ao[g1] = __floats2half2_rn(oacc[nd][2] * inv1, oacc[nd][3] * inv1);
    }
}

// ---------------------------------------------------------------------------
extern "C" void kernel_launch(void* const* d_in, const int* in_sizes, int n_in,
                              void* d_out, int out_size)
{
    const float* x   = (const float*)d_in[0];
    const float* q_w = (const float*)d_in[1];
    const float* q_b = (const float*)d_in[2];
    const float* k_w = (const float*)d_in[3];
    const float* k_b = (const float*)d_in[4];
    const float* v_w = (const float*)d_in[5];
    const float* v_b = (const float*)d_in[6];
    const float* o_w = (const float*)d_in[7];
    const float* o_b = (const float*)d_in[8];
    float* out = (float*)d_out;

    half *xh, *wh, *pqh, *pkh, *pvh, *pao;
    cudaGetSymbolAddress((void**)&xh, g_xh);
    cudaGetSymbolAddress((void**)&wh, g_wh);
    cudaGetSymbolAddress((void**)&pqh, g_qh);
    cudaGetSymbolAddress((void**)&pkh, g_kh);
    cudaGetSymbolAddress((void**)&pvh, g_vh);
    cudaGetSymbolAddress((void**)&pao, g_ao);

    cudaFuncSetAttribute((const void*)gemm_f16<true, 3>,
                         cudaFuncAttributeMaxDynamicSharedMemorySize, SM_GEMM);
    cudaFuncSetAttribute((const void*)gemm_f16<false, 2>,
                         cudaFuncAttributeMaxDynamicSharedMemorySize, SM_GEMM);
    cudaFuncSetAttribute((const void*)attn_mma,
                         cudaFuncAttributeMaxDynamicSharedMemorySize, ASM_TOTAL);

    dim3 cgrid(WN / 2048, 8);   // z 0..3 weights, 4..7 x quarters
    convert_all<<<cgrid, 256>>>(x, q_w, k_w, v_w, o_w, xh, wh);

    dim3 qkv_grid(Cn / 128, Mn / 128, 3);
    gemm_f16<true, 3><<<qkv_grid, 128, SM_GEMM>>>(
        xh, wh, q_b, k_b, v_b, pqh, pkh, pvh, nullptr);

    dim3 attn_grid(Tn / 128, Bn * 16);   // (16, 32) = 512 CTAs
    attn_mma<<<attn_grid, 256, ASM_TOTAL>>>(pqh, pkh, pvh, pao);

    dim3 o_grid(Cn / 128, Mn / 128, 1);
    gemm_f16<false, 2><<<o_grid, 128, SM_GEMM>>>(
        pao, wh + 3 * (size_t)WN, o_b, o_b, o_b,
        nullptr, nullptr, nullptr, out);
}